// round 13
// baseline (speedup 1.0000x reference)
#include <cuda_runtime.h>
#include <cstdint>

#define BATCH 8
#define CC    64
#define CQ    8
#define NN_   4096
#define TMC   128          // m-rows per CTA (8 warps x 16)
#define TN    64           // n-tile
#define NT    (NN_ / TN)
#define THREADS 256

typedef unsigned long long ull;

// fp16 scratch (device globals; no allocation allowed)
__device__ unsigned short g_f16[(size_t)BATCH * NN_ * CQ];  // keys [B][N][8], x log2e
__device__ unsigned short g_g16[(size_t)BATCH * NN_ * CQ];  // query [B][N][8]
__device__ unsigned short g_h16[(size_t)BATCH * NN_ * CC];  // values [B][N][64]

// ---------------------------------------------------------------- helpers
__device__ __forceinline__ uint32_t smem_u32(const void* p) {
    uint32_t a;
    asm("{ .reg .u64 t; cvta.to.shared.u64 t, %1; cvt.u32.u64 %0, t; }"
        : "=r"(a) : "l"(p));
    return a;
}
#define CPA16(dst, src) \
    asm volatile("cp.async.cg.shared.global [%0], [%1], 16;" \
                 :: "r"(dst), "l"(__cvta_generic_to_global(src)))
#define CPCOMMIT() asm volatile("cp.async.commit_group;" ::: "memory")
#define CPWAIT0()  asm volatile("cp.async.wait_group 0;" ::: "memory")

__device__ __forceinline__ void ldsm4(uint32_t& r0, uint32_t& r1,
                                      uint32_t& r2, uint32_t& r3, uint32_t a) {
    asm volatile("ldmatrix.sync.aligned.m8n8.x4.shared.b16 {%0,%1,%2,%3}, [%4];"
                 : "=r"(r0), "=r"(r1), "=r"(r2), "=r"(r3) : "r"(a));
}
__device__ __forceinline__ void ldsm4t(uint32_t& r0, uint32_t& r1,
                                       uint32_t& r2, uint32_t& r3, uint32_t a) {
    asm volatile("ldmatrix.sync.aligned.m8n8.x4.trans.shared.b16 {%0,%1,%2,%3}, [%4];"
                 : "=r"(r0), "=r"(r1), "=r"(r2), "=r"(r3) : "r"(a));
}
// f16 MMA, K=8: S += G x F^T
__device__ __forceinline__ void mma_k8(float* d, uint32_t a0, uint32_t a1,
                                       uint32_t b0) {
    asm volatile("mma.sync.aligned.m16n8k8.row.col.f32.f16.f16.f32 "
                 "{%0,%1,%2,%3},{%4,%5},{%6},{%0,%1,%2,%3};"
                 : "+f"(d[0]), "+f"(d[1]), "+f"(d[2]), "+f"(d[3])
                 : "r"(a0), "r"(a1), "r"(b0));
}
// f16 MMA, K=16: O += W x H
__device__ __forceinline__ void mma_k16(float* d, const uint32_t* a,
                                        uint32_t b0, uint32_t b1) {
    asm volatile("mma.sync.aligned.m16n8k16.row.col.f32.f16.f16.f32 "
                 "{%0,%1,%2,%3},{%4,%5,%6,%7},{%8,%9},{%0,%1,%2,%3};"
                 : "+f"(d[0]), "+f"(d[1]), "+f"(d[2]), "+f"(d[3])
                 : "r"(a[0]), "r"(a[1]), "r"(a[2]), "r"(a[3]), "r"(b0), "r"(b1));
}
__device__ __forceinline__ uint32_t h2pack(float lo, float hi) {
    uint32_t r;
    asm("cvt.rn.f16x2.f32 %0, %1, %2;" : "=r"(r) : "f"(hi), "f"(lo));
    return r;
}

// ---- packed f32x2 ----
__device__ __forceinline__ ull pack2f(float a, float b) {
    ull r; asm("mov.b64 %0, {%1, %2};" : "=l"(r) : "f"(a), "f"(b)); return r;
}
__device__ __forceinline__ void unpack2f(ull v, float& a, float& b) {
    asm("mov.b64 {%0, %1}, %2;" : "=f"(a), "=f"(b) : "l"(v));
}
__device__ __forceinline__ ull ffma2(ull a, ull b, ull c) {
    ull d; asm("fma.rn.f32x2 %0, %1, %2, %3;" : "=l"(d) : "l"(a), "l"(b), "l"(c)); return d;
}
__device__ __forceinline__ ull add2(ull a, ull b) {
    ull d; asm("add.rn.f32x2 %0, %1, %2;" : "=l"(d) : "l"(a), "l"(b)); return d;
}
__device__ __forceinline__ ull mul2(ull a, ull b) {
    ull d; asm("mul.rn.f32x2 %0, %1, %2;" : "=l"(d) : "l"(a), "l"(b)); return d;
}

#define MAGICF 12582912.0f
// degree-3 economized poly for 2^r, r in [-0.5,0.5] (abs err ~1.2e-4)
#define PK0 0.999924865f
#define PK1 0.69314718056f
#define PK2 0.242631045f
#define PK3 0.0555041086648f

// exp2(s - m), m INTEGER-VALUED, folded into constants:
//   C1 = MAGIC - m (exact),  C2 = m - MAGIC (exact)
__device__ __forceinline__ ull exp2_fold(ull s2, ull C1, ull C2) {
    const ull NEGONE2 = pack2f(-1.0f, -1.0f);
    const ull K0 = pack2f(PK0, PK0);
    const ull K1 = pack2f(PK1, PK1);
    const ull K2 = pack2f(PK2, PK2);
    const ull K3 = pack2f(PK3, PK3);
    ull t2 = add2(s2, C1);               // round(s-m) + MAGIC (magic trick)
    ull kf = add2(t2, C2);               // round(s-m) + m   (exact)
    ull r2 = ffma2(kf, NEGONE2, s2);     // (s-m) - round(s-m)
    ull p2 = ffma2(K3, r2, K2);
    p2 = ffma2(p2, r2, K1);
    p2 = ffma2(p2, r2, K0);
    uint32_t tlo = (uint32_t)t2, thi = (uint32_t)(t2 >> 32);
    uint32_t plo = (uint32_t)p2, phi = (uint32_t)(p2 >> 32);
    return (ull)(plo + (tlo << 23)) | ((ull)(phi + (thi << 23)) << 32);
}
// exact 2^d for INTEGER-valued float d (clamped to [-126, 127])
__device__ __forceinline__ float exp2i(float d) {
    d = fmaxf(d, -126.0f);
    int di = (int)d;
    return __uint_as_float((uint32_t)(127 + di) << 23);
}

// ============================================================================
// Kernel 1: projections -> fp16. 256-thread CTAs (8 warps/SM, one wave).
// ============================================================================
__global__ __launch_bounds__(256) void proj_kernel(
    const float* __restrict__ x,
    const float* __restrict__ Wq, const float* __restrict__ bq,
    const float* __restrict__ Wk, const float* __restrict__ bk,
    const float* __restrict__ Wv, const float* __restrict__ bv)
{
    __shared__ __align__(16) float sWq[CQ * CC], sWk[CQ * CC], sWv[CC * CC];
    __shared__ float sbq[CQ], sbk[CQ], sbv[CC];
    int t = threadIdx.x;
    for (int i = t; i < CQ * CC; i += 256) { sWq[i] = Wq[i]; sWk[i] = Wk[i]; }
    for (int i = t; i < CC * CC; i += 256) sWv[i] = Wv[i];
    if (t < CQ) { sbq[t] = bq[t]; sbk[t] = bk[t]; }
    if (t < CC) sbv[t] = bv[t];
    __syncthreads();

    int b = blockIdx.x / (NN_ / 256);
    int n = (blockIdx.x % (NN_ / 256)) * 256 + t;

    float xv[CC];
    const float* xb = x + ((size_t)b * CC) * NN_ + n;
    #pragma unroll
    for (int c = 0; c < CC; c++) xv[c] = xb[(size_t)c * NN_];

    const float LOG2E = 1.4426950408889634f;
    size_t base = (size_t)b * NN_ + n;

    {
        float af[CQ], ag[CQ];
        #pragma unroll
        for (int d = 0; d < CQ; d++) {
            float vf = sbq[d], vg = sbk[d];
            const float4* wq4 = (const float4*)&sWq[d * CC];
            const float4* wk4 = (const float4*)&sWk[d * CC];
            #pragma unroll
            for (int c4 = 0; c4 < CC / 4; c4++) {
                float4 wq = wq4[c4], wk = wk4[c4];
                vf = fmaf(wq.x, xv[4 * c4],     vf);
                vf = fmaf(wq.y, xv[4 * c4 + 1], vf);
                vf = fmaf(wq.z, xv[4 * c4 + 2], vf);
                vf = fmaf(wq.w, xv[4 * c4 + 3], vf);
                vg = fmaf(wk.x, xv[4 * c4],     vg);
                vg = fmaf(wk.y, xv[4 * c4 + 1], vg);
                vg = fmaf(wk.z, xv[4 * c4 + 2], vg);
                vg = fmaf(wk.w, xv[4 * c4 + 3], vg);
            }
            af[d] = vf * LOG2E;
            ag[d] = vg;
        }
        uint4 uf, ug;
        uf.x = h2pack(af[0], af[1]); uf.y = h2pack(af[2], af[3]);
        uf.z = h2pack(af[4], af[5]); uf.w = h2pack(af[6], af[7]);
        ug.x = h2pack(ag[0], ag[1]); ug.y = h2pack(ag[2], ag[3]);
        ug.z = h2pack(ag[4], ag[5]); ug.w = h2pack(ag[6], ag[7]);
        *(uint4*)(g_f16 + base * CQ) = uf;
        *(uint4*)(g_g16 + base * CQ) = ug;
    }

    #pragma unroll
    for (int grp = 0; grp < 8; grp++) {
        float hv[8];
        #pragma unroll
        for (int j = 0; j < 8; j++) {
            int o = grp * 8 + j;
            float a = sbv[o];
            const float4* wv4 = (const float4*)&sWv[o * CC];
            #pragma unroll
            for (int c4 = 0; c4 < CC / 4; c4++) {
                float4 wv = wv4[c4];
                a = fmaf(wv.x, xv[4 * c4],     a);
                a = fmaf(wv.y, xv[4 * c4 + 1], a);
                a = fmaf(wv.z, xv[4 * c4 + 2], a);
                a = fmaf(wv.w, xv[4 * c4 + 3], a);
            }
            hv[j] = a;
        }
        uint4 u;
        u.x = h2pack(hv[0], hv[1]); u.y = h2pack(hv[2], hv[3]);
        u.z = h2pack(hv[4], hv[5]); u.w = h2pack(hv[6], hv[7]);
        *(uint4*)(g_h16 + base * CC + grp * 8) = u;
    }
}

// ============================================================================
// Kernel 2: fp16 flash attention, lazy rescale with INTEGER reference m,
//           folded-magic exp2 (exact bookkeeping).
// ============================================================================
#define HSTR   144
#define H_TILE (64 * HSTR)          // 9216
#define OFF_H0 0
#define OFF_H1 H_TILE
#define OFF_F0 (2 * H_TILE)
#define OFF_F1 (2 * H_TILE + 1024)
#define SMEM_SZ (2 * H_TILE + 2048) // 20480
#define SLACK  8.0f

__global__ __launch_bounds__(THREADS, 2) void attn_kernel(
    const float* __restrict__ x,
    const float* __restrict__ gamma,
    float* __restrict__ out)
{
    __shared__ __align__(128) char smem[SMEM_SZ];
    uint32_t sb = smem_u32(smem);

    int t = threadIdx.x;
    int wid = t >> 5, lane = t & 31;
    int b  = blockIdx.x >> 5;
    int mt = (blockIdx.x & 31) * TMC;
    int mw = mt + wid * 16;
    int r = lane >> 2, q = lane & 3;

    uint32_t hoff = (uint32_t)((lane & 15) * HSTR + (lane >> 4) * 16);

    uint32_t ga0, ga1;
    {
        const uint32_t* gp =
            (const uint32_t*)(g_g16 + ((size_t)b * NN_ + mw) * CQ);
        ga0 = gp[r * 4 + q];
        ga1 = gp[(r + 8) * 4 + q];
    }

    float acc[8][4];
    #pragma unroll
    for (int c = 0; c < 8; c++)
        #pragma unroll
        for (int i = 0; i < 4; i++) acc[c][i] = 0.0f;
    ull l2[2] = {0ULL, 0ULL};
    float m0 = -1e30f, m1 = -1e30f;   // running INTEGER refs (rows r, r+8)
    float m0s = -1e30f, m1s = -1e30f; // m + SLACK (hoisted)
    ull C1_0 = 0, C2_0 = 0, C1_1 = 0, C2_1 = 0;

    const unsigned short* hsrc0 = g_h16 + (size_t)b * NN_ * CC;
    const unsigned short* fsrc0 = g_f16 + (size_t)b * NN_ * CQ;

    auto load_tile = [&](int it) {
        int n0 = it * TN;
        uint32_t hb = sb + ((it & 1) ? OFF_H1 : OFF_H0);
        uint32_t fb = sb + ((it & 1) ? OFF_F1 : OFF_F0);
        #pragma unroll
        for (int p = 0; p < 2; p++) {
            int id = t + p * THREADS;
            int row = id >> 3, ch = id & 7;
            CPA16(hb + row * HSTR + ch * 16,
                  hsrc0 + ((size_t)(n0 + row)) * CC + ch * 8);
        }
        if (t < 64)
            CPA16(fb + t * 16, fsrc0 + ((size_t)(n0 + t)) * CQ);
        CPCOMMIT();
    };

    load_tile(0);

    for (int it = 0; it < NT; it++) {
        CPWAIT0();
        __syncthreads();
        if (it + 1 < NT) load_tile(it + 1);

        uint32_t hb = sb + ((it & 1) ? OFF_H1 : OFF_H0);
        uint32_t fb = sb + ((it & 1) ? OFF_F1 : OFF_F0);

        // ---- GEMM1: S[16m x 64n], f16 K=8 ----
        uint32_t fbr[8];
        ldsm4(fbr[0], fbr[1], fbr[2], fbr[3], fb + lane * 16);
        ldsm4(fbr[4], fbr[5], fbr[6], fbr[7], fb + 512 + lane * 16);
        float s[8][4];
        #pragma unroll
        for (int j = 0; j < 8; j++) {
            #pragma unroll
            for (int i = 0; i < 4; i++) s[j][i] = 0.0f;
            mma_k8(s[j], ga0, ga1, fbr[j]);
        }

        // ---- per-row tile max; rescale only if ref exceeded by > SLACK ----
        float t0 = -1e30f, t1 = -1e30f;
        #pragma unroll
        for (int j = 0; j < 8; j++) {
            t0 = fmaxf(t0, fmaxf(s[j][0], s[j][1]));
            t1 = fmaxf(t1, fmaxf(s[j][2], s[j][3]));
        }
        t0 = fmaxf(t0, __shfl_xor_sync(0xFFFFFFFF, t0, 1));
        t1 = fmaxf(t1, __shfl_xor_sync(0xFFFFFFFF, t1, 1));
        t0 = fmaxf(t0, __shfl_xor_sync(0xFFFFFFFF, t0, 2));
        t1 = fmaxf(t1, __shfl_xor_sync(0xFFFFFFFF, t1, 2));
        bool need = (t0 > m0s) || (t1 > m1s);
        if (__any_sync(0xFFFFFFFF, need)) {
            float m0n = fmaxf(m0, ceilf(t0));   // INTEGER-valued ref
            float m1n = fmaxf(m1, ceilf(t1));
            float sc0 = exp2i(m0 - m0n);        // exact 2^(int delta)
            float sc1 = exp2i(m1 - m1n);
            m0 = m0n; m1 = m1n;
            m0s = m0 + SLACK; m1s = m1 + SLACK;
            C1_0 = pack2f(MAGICF - m0, MAGICF - m0);   // exact
            C2_0 = pack2f(m0 - MAGICF, m0 - MAGICF);
            C1_1 = pack2f(MAGICF - m1, MAGICF - m1);
            C2_1 = pack2f(m1 - MAGICF, m1 - MAGICF);
            l2[0] = mul2(l2[0], pack2f(sc0, sc0));
            l2[1] = mul2(l2[1], pack2f(sc1, sc1));
            #pragma unroll
            for (int c = 0; c < 8; c++) {
                acc[c][0] *= sc0; acc[c][1] *= sc0;
                acc[c][2] *= sc1; acc[c][3] *= sc1;
            }
        }

        // ---- exp2(s - m) -> fp16 A-fragments in registers ----
        uint32_t af[4][4];
        #pragma unroll
        for (int tk = 0; tk < 4; tk++) {
            #pragma unroll
            for (int u = 0; u < 2; u++) {
                int j = 2 * tk + u;
                ull w01 = exp2_fold(pack2f(s[j][0], s[j][1]), C1_0, C2_0);
                ull w23 = exp2_fold(pack2f(s[j][2], s[j][3]), C1_1, C2_1);
                l2[0] = add2(l2[0], w01);
                l2[1] = add2(l2[1], w23);
                float wa, wb;
                unpack2f(w01, wa, wb);
                af[tk][2 * u]     = h2pack(wa, wb);
                unpack2f(w23, wa, wb);
                af[tk][2 * u + 1] = h2pack(wa, wb);
            }
        }

        // ---- GEMM2: O += W x H, f16 K=16, H via ldsm.trans ----
        #pragma unroll
        for (int tk = 0; tk < 4; tk++) {
            uint32_t hbase = hb + tk * 16 * HSTR + hoff;
            #pragma unroll
            for (int cb = 0; cb < 4; cb++) {
                uint32_t b0, b1, b2, b3;
                ldsm4t(b0, b1, b2, b3, hbase + cb * 32);
                mma_k16(acc[2 * cb],     af[tk], b0, b1);
                mma_k16(acc[2 * cb + 1], af[tk], b2, b3);
            }
        }
    }

    // ---- l reduction (warp-local quad) ----
    float scale0, scale1;
    {
        float gm = gamma[0];
        float lo, hi;
        unpack2f(l2[0], lo, hi);
        float la = lo + hi;
        la += __shfl_xor_sync(0xFFFFFFFF, la, 1);
        la += __shfl_xor_sync(0xFFFFFFFF, la, 2);
        unpack2f(l2[1], lo, hi);
        float lb = lo + hi;
        lb += __shfl_xor_sync(0xFFFFFFFF, lb, 1);
        lb += __shfl_xor_sync(0xFFFFFFFF, lb, 2);
        scale0 = gm / la;
        scale1 = gm / lb;
    }

    // ---- epilogue ----
    const float* xb = x   + (size_t)b * CC * NN_;
    float*       ob = out + (size_t)b * CC * NN_;
    int m0g = mw + r;
    #pragma unroll
    for (int cs = 0; cs < 8; cs++) {
        int c = cs * 8 + 2 * q;
        size_t a00 = (size_t)c * NN_ + m0g;
        size_t a01 = a00 + NN_;
        ob[a00]     = fmaf(acc[cs][0], scale0, xb[a00]);
        ob[a01]     = fmaf(acc[cs][1], scale0, xb[a01]);
        ob[a00 + 8] = fmaf(acc[cs][2], scale1, xb[a00 + 8]);
        ob[a01 + 8] = fmaf(acc[cs][3], scale1, xb[a01 + 8]);
    }
}

// ============================================================================
extern "C" void kernel_launch(void* const* d_in, const int* in_sizes, int n_in,
                              void* d_out, int out_size)
{
    const float* x     = (const float*)d_in[0];
    const float* Wq    = (const float*)d_in[1];
    const float* bq    = (const float*)d_in[2];
    const float* Wk    = (const float*)d_in[3];
    const float* bk    = (const float*)d_in[4];
    const float* Wv    = (const float*)d_in[5];
    const float* bv    = (const float*)d_in[6];
    const float* gamma = (const float*)d_in[7];
    float* out = (float*)d_out;

    proj_kernel<<<BATCH * NN_ / 256, 256>>>(x, Wq, bq, Wk, bk, Wv, bv);
    attn_kernel<<<BATCH * NN_ / TMC, THREADS>>>(x, gamma, out);
}

// round 14
// speedup vs baseline: 1.0510x; 1.0510x over previous
#include <cuda_runtime.h>
#include <cstdint>

#define BATCH 8
#define CC    64
#define CQ    8
#define NN_   4096
#define TMC   256          // m-rows per CTA (16 warps x 16)
#define TN    64           // n-tile
#define NT    (NN_ / TN)
#define THREADS 512

typedef unsigned long long ull;

// fp16 scratch (device globals; no allocation allowed)
__device__ unsigned short g_f16[(size_t)BATCH * NN_ * CQ];  // keys [B][N][8], x log2e
__device__ unsigned short g_g16[(size_t)BATCH * NN_ * CQ];  // query [B][N][8]
__device__ unsigned short g_h16[(size_t)BATCH * NN_ * CC];  // values [B][N][64]

// ---------------------------------------------------------------- helpers
__device__ __forceinline__ uint32_t smem_u32(const void* p) {
    uint32_t a;
    asm("{ .reg .u64 t; cvta.to.shared.u64 t, %1; cvt.u32.u64 %0, t; }"
        : "=r"(a) : "l"(p));
    return a;
}
#define CPA16(dst, src) \
    asm volatile("cp.async.cg.shared.global [%0], [%1], 16;" \
                 :: "r"(dst), "l"(__cvta_generic_to_global(src)))
#define CPCOMMIT() asm volatile("cp.async.commit_group;" ::: "memory")
#define CPWAIT0()  asm volatile("cp.async.wait_group 0;" ::: "memory")

__device__ __forceinline__ void ldsm4(uint32_t& r0, uint32_t& r1,
                                      uint32_t& r2, uint32_t& r3, uint32_t a) {
    asm volatile("ldmatrix.sync.aligned.m8n8.x4.shared.b16 {%0,%1,%2,%3}, [%4];"
                 : "=r"(r0), "=r"(r1), "=r"(r2), "=r"(r3) : "r"(a));
}
__device__ __forceinline__ void ldsm4t(uint32_t& r0, uint32_t& r1,
                                       uint32_t& r2, uint32_t& r3, uint32_t a) {
    asm volatile("ldmatrix.sync.aligned.m8n8.x4.trans.shared.b16 {%0,%1,%2,%3}, [%4];"
                 : "=r"(r0), "=r"(r1), "=r"(r2), "=r"(r3) : "r"(a));
}
// f16 MMA, K=8: S += G x F^T
__device__ __forceinline__ void mma_k8(float* d, uint32_t a0, uint32_t a1,
                                       uint32_t b0) {
    asm volatile("mma.sync.aligned.m16n8k8.row.col.f32.f16.f16.f32 "
                 "{%0,%1,%2,%3},{%4,%5},{%6},{%0,%1,%2,%3};"
                 : "+f"(d[0]), "+f"(d[1]), "+f"(d[2]), "+f"(d[3])
                 : "r"(a0), "r"(a1), "r"(b0));
}
// f16 MMA, K=16: O += W x H
__device__ __forceinline__ void mma_k16(float* d, const uint32_t* a,
                                        uint32_t b0, uint32_t b1) {
    asm volatile("mma.sync.aligned.m16n8k16.row.col.f32.f16.f16.f32 "
                 "{%0,%1,%2,%3},{%4,%5,%6,%7},{%8,%9},{%0,%1,%2,%3};"
                 : "+f"(d[0]), "+f"(d[1]), "+f"(d[2]), "+f"(d[3])
                 : "r"(a[0]), "r"(a[1]), "r"(a[2]), "r"(a[3]), "r"(b0), "r"(b1));
}
__device__ __forceinline__ uint32_t h2pack(float lo, float hi) {
    uint32_t r;
    asm("cvt.rn.f16x2.f32 %0, %1, %2;" : "=r"(r) : "f"(hi), "f"(lo));
    return r;
}

// ---- packed f32x2 ----
__device__ __forceinline__ ull pack2f(float a, float b) {
    ull r; asm("mov.b64 %0, {%1, %2};" : "=l"(r) : "f"(a), "f"(b)); return r;
}
__device__ __forceinline__ void unpack2f(ull v, float& a, float& b) {
    asm("mov.b64 {%0, %1}, %2;" : "=f"(a), "=f"(b) : "l"(v));
}
__device__ __forceinline__ ull ffma2(ull a, ull b, ull c) {
    ull d; asm("fma.rn.f32x2 %0, %1, %2, %3;" : "=l"(d) : "l"(a), "l"(b), "l"(c)); return d;
}
__device__ __forceinline__ ull add2(ull a, ull b) {
    ull d; asm("add.rn.f32x2 %0, %1, %2;" : "=l"(d) : "l"(a), "l"(b)); return d;
}

#define MAGICF 12582912.0f
// degree-3 economized poly for 2^r, r in [-0.5,0.5] (abs err ~1.2e-4)
#define PK0 0.999924865f
#define PK1 0.69314718056f
#define PK2 0.242631045f
#define PK3 0.0555041086648f
#define ONES_H2 0x3C003C00u   // (1.0h, 1.0h)

// exp2(s - m), m INTEGER-VALUED, folded into constants:
//   C1 = MAGIC - m (exact),  C2 = m - MAGIC (exact)
__device__ __forceinline__ ull exp2_fold(ull s2, ull C1, ull C2) {
    const ull NEGONE2 = pack2f(-1.0f, -1.0f);
    const ull K0 = pack2f(PK0, PK0);
    const ull K1 = pack2f(PK1, PK1);
    const ull K2 = pack2f(PK2, PK2);
    const ull K3 = pack2f(PK3, PK3);
    ull t2 = add2(s2, C1);               // round(s-m) + MAGIC (magic trick)
    ull kf = add2(t2, C2);               // round(s-m) + m   (exact)
    ull r2 = ffma2(kf, NEGONE2, s2);     // (s-m) - round(s-m)
    ull p2 = ffma2(K3, r2, K2);
    p2 = ffma2(p2, r2, K1);
    p2 = ffma2(p2, r2, K0);
    uint32_t tlo = (uint32_t)t2, thi = (uint32_t)(t2 >> 32);
    uint32_t plo = (uint32_t)p2, phi = (uint32_t)(p2 >> 32);
    return (ull)(plo + (tlo << 23)) | ((ull)(phi + (thi << 23)) << 32);
}
// exact 2^d for INTEGER-valued float d (clamped to [-126, 127])
__device__ __forceinline__ float exp2i(float d) {
    d = fmaxf(d, -126.0f);
    int di = (int)d;
    return __uint_as_float((uint32_t)(127 + di) << 23);
}

// ============================================================================
// Kernel 1: projections -> fp16, channel-split across CTA pairs.
//   parity 0: f, g, h[0:24];  parity 1: h[24:64]
// ============================================================================
__global__ __launch_bounds__(256) void proj_kernel(
    const float* __restrict__ x,
    const float* __restrict__ Wq, const float* __restrict__ bq,
    const float* __restrict__ Wk, const float* __restrict__ bk,
    const float* __restrict__ Wv, const float* __restrict__ bv)
{
    __shared__ __align__(16) float sWq[CQ * CC], sWk[CQ * CC], sWv[CC * CC];
    __shared__ float sbq[CQ], sbk[CQ], sbv[CC];
    int t = threadIdx.x;
    int parity = blockIdx.x & 1;
    int blk = blockIdx.x >> 1;

    if (parity == 0)
        for (int i = t; i < CQ * CC; i += 256) { sWq[i] = Wq[i]; sWk[i] = Wk[i]; }
    int vlo = parity ? 24 * CC : 0;
    int vhi = parity ? 64 * CC : 24 * CC;
    for (int i = vlo + t; i < vhi; i += 256) sWv[i] = Wv[i];
    if (t < CQ) { sbq[t] = bq[t]; sbk[t] = bk[t]; }
    if (t < CC) sbv[t] = bv[t];
    __syncthreads();

    int b = blk / (NN_ / 256);
    int n = (blk % (NN_ / 256)) * 256 + t;

    float xv[CC];
    const float* xb = x + ((size_t)b * CC) * NN_ + n;
    #pragma unroll
    for (int c = 0; c < CC; c++) xv[c] = xb[(size_t)c * NN_];

    const float LOG2E = 1.4426950408889634f;
    size_t base = (size_t)b * NN_ + n;

    if (parity == 0) {
        float af[CQ], ag[CQ];
        #pragma unroll
        for (int d = 0; d < CQ; d++) {
            float vf = sbq[d], vg = sbk[d];
            const float4* wq4 = (const float4*)&sWq[d * CC];
            const float4* wk4 = (const float4*)&sWk[d * CC];
            #pragma unroll
            for (int c4 = 0; c4 < CC / 4; c4++) {
                float4 wq = wq4[c4], wk = wk4[c4];
                vf = fmaf(wq.x, xv[4 * c4],     vf);
                vf = fmaf(wq.y, xv[4 * c4 + 1], vf);
                vf = fmaf(wq.z, xv[4 * c4 + 2], vf);
                vf = fmaf(wq.w, xv[4 * c4 + 3], vf);
                vg = fmaf(wk.x, xv[4 * c4],     vg);
                vg = fmaf(wk.y, xv[4 * c4 + 1], vg);
                vg = fmaf(wk.z, xv[4 * c4 + 2], vg);
                vg = fmaf(wk.w, xv[4 * c4 + 3], vg);
            }
            af[d] = vf * LOG2E;
            ag[d] = vg;
        }
        uint4 uf, ug;
        uf.x = h2pack(af[0], af[1]); uf.y = h2pack(af[2], af[3]);
        uf.z = h2pack(af[4], af[5]); uf.w = h2pack(af[6], af[7]);
        ug.x = h2pack(ag[0], ag[1]); ug.y = h2pack(ag[2], ag[3]);
        ug.z = h2pack(ag[4], ag[5]); ug.w = h2pack(ag[6], ag[7]);
        *(uint4*)(g_f16 + base * CQ) = uf;
        *(uint4*)(g_g16 + base * CQ) = ug;
    }

    int glo = parity ? 3 : 0;
    int ghi = parity ? 8 : 3;
    for (int grp = glo; grp < ghi; grp++) {
        float hv[8];
        #pragma unroll
        for (int j = 0; j < 8; j++) {
            int o = grp * 8 + j;
            float a = sbv[o];
            const float4* wv4 = (const float4*)&sWv[o * CC];
            #pragma unroll
            for (int c4 = 0; c4 < CC / 4; c4++) {
                float4 wv = wv4[c4];
                a = fmaf(wv.x, xv[4 * c4],     a);
                a = fmaf(wv.y, xv[4 * c4 + 1], a);
                a = fmaf(wv.z, xv[4 * c4 + 2], a);
                a = fmaf(wv.w, xv[4 * c4 + 3], a);
            }
            hv[j] = a;
        }
        uint4 u;
        u.x = h2pack(hv[0], hv[1]); u.y = h2pack(hv[2], hv[3]);
        u.z = h2pack(hv[4], hv[5]); u.w = h2pack(hv[6], hv[7]);
        *(uint4*)(g_h16 + base * CC + grp * 8) = u;
    }
}

// ============================================================================
// Kernel 2: fp16 flash attention. TMC=256 (1 CTA/SM) halves per-SM cp.async;
//           l computed by GEMM2 against a constant all-ones B fragment.
// ============================================================================
#define HSTR   144
#define H_TILE (64 * HSTR)          // 9216
#define OFF_H0 0
#define OFF_H1 H_TILE
#define OFF_F0 (2 * H_TILE)
#define OFF_F1 (2 * H_TILE + 1024)
#define SMEM_SZ (2 * H_TILE + 2048) // 20480
#define SLACK  8.0f

__global__ __launch_bounds__(THREADS, 1) void attn_kernel(
    const float* __restrict__ x,
    const float* __restrict__ gamma,
    float* __restrict__ out)
{
    __shared__ __align__(128) char smem[SMEM_SZ];
    uint32_t sb = smem_u32(smem);

    int t = threadIdx.x;
    int wid = t >> 5, lane = t & 31;
    int b  = blockIdx.x >> 4;                // 16 m-tiles per batch
    int mt = (blockIdx.x & 15) * TMC;
    int mw = mt + wid * 16;
    int r = lane >> 2, q = lane & 3;

    uint32_t hoff = (uint32_t)((lane & 15) * HSTR + (lane >> 4) * 16);

    uint32_t ga0, ga1;
    {
        const uint32_t* gp =
            (const uint32_t*)(g_g16 + ((size_t)b * NN_ + mw) * CQ);
        ga0 = gp[r * 4 + q];
        ga1 = gp[(r + 8) * 4 + q];
    }

    float acc[8][4];
    #pragma unroll
    for (int c = 0; c < 8; c++)
        #pragma unroll
        for (int i = 0; i < 4; i++) acc[c][i] = 0.0f;
    float lacc[4] = {0.0f, 0.0f, 0.0f, 0.0f};   // l via ones-GEMM
    float m0 = -1e30f, m1 = -1e30f;   // running INTEGER refs (rows r, r+8)
    float m0s = -1e30f, m1s = -1e30f; // m + SLACK (hoisted)
    ull C1_0 = 0, C2_0 = 0, C1_1 = 0, C2_1 = 0;

    const unsigned short* hsrc0 = g_h16 + (size_t)b * NN_ * CC;
    const unsigned short* fsrc0 = g_f16 + (size_t)b * NN_ * CQ;

    auto load_tile = [&](int it) {
        int n0 = it * TN;
        uint32_t hb = sb + ((it & 1) ? OFF_H1 : OFF_H0);
        uint32_t fb = sb + ((it & 1) ? OFF_F1 : OFF_F0);
        // H: 64 rows x 8 chunks = 512 cp16, one per thread
        {
            int row = t >> 3, ch = t & 7;
            CPA16(hb + row * HSTR + ch * 16,
                  hsrc0 + ((size_t)(n0 + row)) * CC + ch * 8);
        }
        if (t < 64)
            CPA16(fb + t * 16, fsrc0 + ((size_t)(n0 + t)) * CQ);
        CPCOMMIT();
    };

    load_tile(0);

    for (int it = 0; it < NT; it++) {
        CPWAIT0();
        __syncthreads();
        if (it + 1 < NT) load_tile(it + 1);

        uint32_t hb = sb + ((it & 1) ? OFF_H1 : OFF_H0);
        uint32_t fb = sb + ((it & 1) ? OFF_F1 : OFF_F0);

        // ---- GEMM1: S[16m x 64n], f16 K=8 ----
        uint32_t fbr[8];
        ldsm4(fbr[0], fbr[1], fbr[2], fbr[3], fb + lane * 16);
        ldsm4(fbr[4], fbr[5], fbr[6], fbr[7], fb + 512 + lane * 16);
        float s[8][4];
        #pragma unroll
        for (int j = 0; j < 8; j++) {
            #pragma unroll
            for (int i = 0; i < 4; i++) s[j][i] = 0.0f;
            mma_k8(s[j], ga0, ga1, fbr[j]);
        }

        // ---- per-row tile max; rescale only if ref exceeded by > SLACK ----
        float t0 = -1e30f, t1 = -1e30f;
        #pragma unroll
        for (int j = 0; j < 8; j++) {
            t0 = fmaxf(t0, fmaxf(s[j][0], s[j][1]));
            t1 = fmaxf(t1, fmaxf(s[j][2], s[j][3]));
        }
        t0 = fmaxf(t0, __shfl_xor_sync(0xFFFFFFFF, t0, 1));
        t1 = fmaxf(t1, __shfl_xor_sync(0xFFFFFFFF, t1, 1));
        t0 = fmaxf(t0, __shfl_xor_sync(0xFFFFFFFF, t0, 2));
        t1 = fmaxf(t1, __shfl_xor_sync(0xFFFFFFFF, t1, 2));
        bool need = (t0 > m0s) || (t1 > m1s);
        if (__any_sync(0xFFFFFFFF, need)) {
            float m0n = fmaxf(m0, ceilf(t0));   // INTEGER-valued ref
            float m1n = fmaxf(m1, ceilf(t1));
            float sc0 = exp2i(m0 - m0n);        // exact 2^(int delta)
            float sc1 = exp2i(m1 - m1n);
            m0 = m0n; m1 = m1n;
            m0s = m0 + SLACK; m1s = m1 + SLACK;
            C1_0 = pack2f(MAGICF - m0, MAGICF - m0);   // exact
            C2_0 = pack2f(m0 - MAGICF, m0 - MAGICF);
            C1_1 = pack2f(MAGICF - m1, MAGICF - m1);
            C2_1 = pack2f(m1 - MAGICF, m1 - MAGICF);
            lacc[0] *= sc0; lacc[1] *= sc0;
            lacc[2] *= sc1; lacc[3] *= sc1;
            #pragma unroll
            for (int c = 0; c < 8; c++) {
                acc[c][0] *= sc0; acc[c][1] *= sc0;
                acc[c][2] *= sc1; acc[c][3] *= sc1;
            }
        }

        // ---- exp2(s - m) -> fp16 A-fragments in registers ----
        uint32_t af[4][4];
        #pragma unroll
        for (int tk = 0; tk < 4; tk++) {
            #pragma unroll
            for (int u = 0; u < 2; u++) {
                int j = 2 * tk + u;
                ull w01 = exp2_fold(pack2f(s[j][0], s[j][1]), C1_0, C2_0);
                ull w23 = exp2_fold(pack2f(s[j][2], s[j][3]), C1_1, C2_1);
                float wa, wb;
                unpack2f(w01, wa, wb);
                af[tk][2 * u]     = h2pack(wa, wb);
                unpack2f(w23, wa, wb);
                af[tk][2 * u + 1] = h2pack(wa, wb);
            }
        }

        // ---- GEMM2: O += W x H (K=16) + l += W x ones ----
        #pragma unroll
        for (int tk = 0; tk < 4; tk++) {
            uint32_t hbase = hb + tk * 16 * HSTR + hoff;
            #pragma unroll
            for (int cb = 0; cb < 4; cb++) {
                uint32_t b0, b1, b2, b3;
                ldsm4t(b0, b1, b2, b3, hbase + cb * 32);
                mma_k16(acc[2 * cb],     af[tk], b0, b1);
                mma_k16(acc[2 * cb + 1], af[tk], b2, b3);
            }
            mma_k16(lacc, af[tk], ONES_H2, ONES_H2);   // row sums -> l
        }
    }

    // ---- scales straight from lacc (no reductions needed) ----
    float gm = gamma[0];
    float scale0 = gm / lacc[0];
    float scale1 = gm / lacc[2];

    // ---- epilogue ----
    const float* xb = x   + (size_t)b * CC * NN_;
    float*       ob = out + (size_t)b * CC * NN_;
    int m0g = mw + r;
    #pragma unroll
    for (int cs = 0; cs < 8; cs++) {
        int c = cs * 8 + 2 * q;
        size_t a00 = (size_t)c * NN_ + m0g;
        size_t a01 = a00 + NN_;
        ob[a00]     = fmaf(acc[cs][0], scale0, xb[a00]);
        ob[a01]     = fmaf(acc[cs][1], scale0, xb[a01]);
        ob[a00 + 8] = fmaf(acc[cs][2], scale1, xb[a00 + 8]);
        ob[a01 + 8] = fmaf(acc[cs][3], scale1, xb[a01 + 8]);
    }
}

// ============================================================================
extern "C" void kernel_launch(void* const* d_in, const int* in_sizes, int n_in,
                              void* d_out, int out_size)
{
    const float* x     = (const float*)d_in[0];
    const float* Wq    = (const float*)d_in[1];
    const float* bq    = (const float*)d_in[2];
    const float* Wk    = (const float*)d_in[3];
    const float* bk    = (const float*)d_in[4];
    const float* Wv    = (const float*)d_in[5];
    const float* bv    = (const float*)d_in[6];
    const float* gamma = (const float*)d_in[7];
    float* out = (float*)d_out;

    proj_kernel<<<2 * BATCH * NN_ / 256, 256>>>(x, Wq, bq, Wk, bk, Wv, bv);
    attn_kernel<<<BATCH * NN_ / TMC, THREADS>>>(x, gamma, out);
}